// round 8
// baseline (speedup 1.0000x reference)
#include <cuda_runtime.h>

namespace {

constexpr int H  = 64;
constexpr int Fd = 8;
constexpr int Tn = 512;
constexpr int Pn = 64;
constexpr int NT = 256;
constexpr int NBMAX = 4;
constexpr int HP  = 72;           // h row stride -> conflict-free stores
constexpr int SGS = 260;          // sg row stride (floats)
constexpr int QS  = NBMAX * SGS;  // sg quarter stride
constexpr int SGH = 4 * QS;       // sg ping-pong offset

using u64 = unsigned long long;

__device__ __forceinline__ u64 ffma2(u64 a, u64 b, u64 c) {
    u64 d;
    asm("fma.rn.f32x2 %0, %1, %2, %3;" : "=l"(d) : "l"(a), "l"(b), "l"(c));
    return d;
}
__device__ __forceinline__ float hsum2(u64 v) {
    float lo, hi;
    asm("mov.b64 {%0, %1}, %2;" : "=f"(lo), "=f"(hi) : "l"(v));
    return lo + hi;
}
__device__ __forceinline__ float tanh_a(float x) {
    float y;
    asm("tanh.approx.f32 %0, %1;" : "=f"(y) : "f"(x));
    return y;
}
__device__ __forceinline__ float sig_a(float x) {
    return fmaf(tanh_a(0.5f * x), 0.5f, 0.5f);
}
__device__ __forceinline__ void bar_sync(int id, int cnt) {
    asm volatile("bar.sync %0, %1;" :: "r"(id), "r"(cnt) : "memory");
}
__device__ __forceinline__ void bar_arrive(int id, int cnt) {
    asm volatile("bar.arrive %0, %1;" :: "r"(id), "r"(cnt) : "memory");
}

// Per-thread weights: 4 gate rows of unit U, k-quarter q (chunk-rotated).
struct WReg {
    u64  wh[4][8];
    u64  wx[4];
    float bi[4];
};

__device__ __forceinline__ void load_w(
    const float* __restrict__ Whh, const float* __restrict__ Wih,
    const float* __restrict__ bih, const float* __restrict__ bhh,
    int U, int q, WReg& W)
{
#pragma unroll
    for (int g = 0; g < 4; g++) {
        const int row = 64 * g + U;
        const float* base = Whh + row * H + 16 * q;
#pragma unroll
        for (int c = 0; c < 4; c++) {
            const int cc = (c + q) & 3;
            ulonglong2 v = __ldg((const ulonglong2*)(base + 4 * cc));
            W.wh[g][2 * c]     = v.x;
            W.wh[g][2 * c + 1] = v.y;
        }
        W.wx[g] = __ldg((const u64*)(Wih + row * Fd) + q);
        W.bi[g] = bih[row] + bhh[row];
    }
}

// Partials for all NB_ rows; x from registers; writes float4 per (b,U) to sgq.
template<int NB_>
__device__ __forceinline__ void gate_partials(
    const WReg& W, const float (*__restrict__ sh)[HP],
    const u64* __restrict__ xc,
    float* __restrict__ sgq, int U, int q)
{
#pragma unroll
    for (int b = 0; b < NB_; b++) {
        u64 a0 = 0, a1 = 0, a2 = 0, a3 = 0;
        const u64 xv = xc[b];
        a0 = ffma2(W.wx[0], xv, a0);
        a1 = ffma2(W.wx[1], xv, a1);
        a2 = ffma2(W.wx[2], xv, a2);
        a3 = ffma2(W.wx[3], xv, a3);
        const float* hb = &sh[b][16 * q];
#pragma unroll
        for (int c = 0; c < 4; c++) {
            const int cc = (c + q) & 3;
            ulonglong2 hv = *(const ulonglong2*)(hb + 4 * cc);
            a0 = ffma2(W.wh[0][2 * c], hv.x, a0);
            a1 = ffma2(W.wh[1][2 * c], hv.x, a1);
            a2 = ffma2(W.wh[2][2 * c], hv.x, a2);
            a3 = ffma2(W.wh[3][2 * c], hv.x, a3);
            a0 = ffma2(W.wh[0][2 * c + 1], hv.y, a0);
            a1 = ffma2(W.wh[1][2 * c + 1], hv.y, a1);
            a2 = ffma2(W.wh[2][2 * c + 1], hv.y, a2);
            a3 = ffma2(W.wh[3][2 * c + 1], hv.y, a3);
        }
        *(float4*)&sgq[b * SGS + U * 4] =
            make_float4(hsum2(a0), hsum2(a1), hsum2(a2), hsum2(a3));
    }
}

__device__ __forceinline__ void activation(
    const float* __restrict__ sgh, const WReg& W,
    float (*__restrict__ shB)[HP], int U, int r, float& c)
{
    const int base = r * SGS + U * 4;
    float4 s0 = *(const float4*)&sgh[0 * QS + base];
    float4 s1 = *(const float4*)&sgh[1 * QS + base];
    float4 s2 = *(const float4*)&sgh[2 * QS + base];
    float4 s3 = *(const float4*)&sgh[3 * QS + base];
    float gi = s0.x + s1.x + s2.x + s3.x + W.bi[0];
    float gf = s0.y + s1.y + s2.y + s3.y + W.bi[1];
    float gg = s0.z + s1.z + s2.z + s3.z + W.bi[2];
    float go = s0.w + s1.w + s2.w + s3.w + W.bi[3];
    c = sig_a(gf) * c + sig_a(gi) * tanh_a(gg);
    shB[r][U] = sig_a(go) * tanh_a(c);
}

template<int NB_>
__device__ __forceinline__ void run_lstm(
    int b0,
    const float* __restrict__ input,
    const float* __restrict__ eWih, const float* __restrict__ eWhh,
    const float* __restrict__ ebih, const float* __restrict__ ebhh,
    const float* __restrict__ dWih, const float* __restrict__ dWhh,
    const float* __restrict__ dbih, const float* __restrict__ dbhh,
    const float* __restrict__ fcW,  const float* __restrict__ fcb,
    float* __restrict__ out,
    float (*__restrict__ sh0)[HP], float (*__restrict__ sh1)[HP],
    float* __restrict__ sg,
    float (*__restrict__ sx)[Fd],
    float (*__restrict__ sfcW)[H], float* __restrict__ sfcb)
{
    const int tid  = threadIdx.x;
    const int lane = tid & 31;
    const int wrp  = tid >> 5;
    const int q    = wrp & 3;            // k-quarter (warp-uniform) & activation row
    const int hh   = wrp >> 2;           // unit half owned
    const int U    = 32 * hh + lane;     // unit (0..63)
    const int r    = q;                  // activation batch row
    const int BG   = 1 + hh;             // group partials barrier (128)
    const int BHp  = 3 + hh;             // h-half barrier: producer role
    const int BHc  = 3 + (q >> 1);       // h-half barrier: consumer role

    ((float*)sfcW)[tid]      = fcW[tid];
    ((float*)sfcW)[tid + NT] = fcW[tid + NT];
    if (tid < Fd) sfcb[tid] = fcb[tid];

    if (r < NB_) sh0[r][U] = 0.0f;
    float c = 0.0f;

    WReg W;
    load_w(eWhh, eWih, ebih, ebhh, U, q, W);

    // x base pointers: warp-uniform broadcast loads (2 feats [2q,2q+1])
    const u64* xp[NBMAX];
#pragma unroll
    for (int b = 0; b < NB_; b++)
        xp[b] = (const u64*)(input + (size_t)(b0 + b) * Tn * Fd + 2 * q);

    u64 xc[NBMAX], xn[NBMAX];
#pragma unroll
    for (int b = 0; b < NB_; b++) xc[b] = __ldg(xp[b]);   // x(0)

    float (*shA)[HP] = sh0;
    float (*shB)[HP] = sh1;

    __syncthreads();             // h-zero + fcW visible
    bar_arrive(BHp, 256);        // prologue: publish h(-1)=0 for my half

    // ============ encoder: group-decoupled named barriers ============
    for (int t = 0; t < Tn; t++) {
        if (t + 1 < Tn) {
#pragma unroll
            for (int b = 0; b < NB_; b++) xn[b] = __ldg(xp[b] + (size_t)(t + 1) * 4);
        }
        bar_sync(BHc, 256);      // my h-half (prev step) published

        gate_partials<NB_>(W, shA, xc, sg + (t & 1) * SGH + q * QS, U, q);
#pragma unroll
        for (int b = 0; b < NB_; b++) xc[b] = xn[b];

        bar_sync(BG, 128);       // group partials rendezvous
        if (r < NB_) activation(sg + (t & 1) * SGH, W, shB, U, r, c);
        bar_arrive(BHp, 256);    // publish my h-half

        float (*tmp)[HP] = shA; shA = shB; shB = tmp;
    }

    // ============ decoder: simple full barriers (64 steps) ============
    load_w(dWhh, dWih, dbih, dbhh, U, q, W);

    const bool xth = tid < NB_ * Fd;
    const int  xb  = tid >> 3;
    const int  xf  = tid & 7;
    if (xth)   // x_last = input[:, T-1, :]
        sx[xb][xf] = __ldg(input + ((size_t)(b0 + xb) * Tn + (Tn - 1)) * Fd + xf);

    for (int p = 0; p < Pn; p++) {
        __syncthreads();         // h in shA, x in sx
        u64 xv[NBMAX];
#pragma unroll
        for (int b = 0; b < NB_; b++) xv[b] = *(const u64*)&sx[b][2 * q];

        gate_partials<NB_>(W, shA, xv, sg + q * QS, U, q);
        __syncthreads();         // partials ready

        if (r < NB_) activation(sg, W, shB, U, r, c);
        __syncthreads();         // h_new ready

        if (xth) {               // pred = h_new @ fcW^T + fcb
            float a = sfcb[xf];
            const float4* hr = (const float4*)&shB[xb][0];
            const float4* wr = (const float4*)&sfcW[xf][0];
#pragma unroll
            for (int k = 0; k < 16; k++) {
                float4 hv = hr[k], wv = wr[k];
                a = fmaf(hv.x, wv.x, a);
                a = fmaf(hv.y, wv.y, a);
                a = fmaf(hv.z, wv.z, a);
                a = fmaf(hv.w, wv.w, a);
            }
            out[((size_t)(b0 + xb) * Pn + p) * Fd + xf] = a;
            sx[xb][xf] = a;
        }
        float (*tmp)[HP] = shA; shA = shB; shB = tmp;
    }
}

__global__ void __launch_bounds__(NT, 2)
seq2seq_lstm_kernel(
    const float* __restrict__ input,
    const float* __restrict__ eWih, const float* __restrict__ eWhh,
    const float* __restrict__ ebih, const float* __restrict__ ebhh,
    const float* __restrict__ dWih, const float* __restrict__ dWhh,
    const float* __restrict__ dbih, const float* __restrict__ dbhh,
    const float* __restrict__ fcW,  const float* __restrict__ fcb,
    float* __restrict__ out)
{
    __shared__ float sh0[NBMAX][HP];
    __shared__ float sh1[NBMAX][HP];
    __shared__ float sg[2 * SGH];
    __shared__ float sx[NBMAX][Fd];
    __shared__ float sfcW[Fd][H];
    __shared__ float sfcb[Fd];

    const int bid = blockIdx.x;
    if (bid < 136) {
        run_lstm<4>(4 * bid, input, eWih, eWhh, ebih, ebhh,
                    dWih, dWhh, dbih, dbhh, fcW, fcb, out,
                    sh0, sh1, sg, sx, sfcW, sfcb);
    } else {
        int b0 = (bid < 148) ? (544 + 3 * (bid - 136))
                             : (580 + 3 * (bid - 148));
        run_lstm<3>(b0, input, eWih, eWhh, ebih, ebhh,
                    dWih, dWhh, dbih, dbhh, fcW, fcb, out,
                    sh0, sh1, sg, sx, sfcW, sfcb);
    }
}

} // anonymous namespace

extern "C" void kernel_launch(void* const* d_in, const int* in_sizes, int n_in,
                              void* d_out, int out_size)
{
    const float* input = (const float*)d_in[0];
    const float* eWih  = (const float*)d_in[1];
    const float* eWhh  = (const float*)d_in[2];
    const float* ebih  = (const float*)d_in[3];
    const float* ebhh  = (const float*)d_in[4];
    const float* dWih  = (const float*)d_in[5];
    const float* dWhh  = (const float*)d_in[6];
    const float* dbih  = (const float*)d_in[7];
    const float* dbhh  = (const float*)d_in[8];
    const float* fcW   = (const float*)d_in[9];
    const float* fcb   = (const float*)d_in[10];
    float* out = (float*)d_out;

    seq2seq_lstm_kernel<<<296, NT>>>(input, eWih, eWhh, ebih, ebhh,
                                     dWih, dWhh, dbih, dbhh, fcW, fcb, out);
}

// round 9
// speedup vs baseline: 1.0006x; 1.0006x over previous
#include <cuda_runtime.h>

namespace {

constexpr int H  = 64;
constexpr int Fd = 8;
constexpr int Tn = 512;
constexpr int Pn = 64;
constexpr int NT = 256;
constexpr int NBMAX = 4;
constexpr int HP  = 72;           // h row stride -> conflict-free stores
constexpr int SGS = 260;          // sg row stride (floats)
constexpr int QS  = NBMAX * SGS;  // sg quarter stride
constexpr int SGH = 4 * QS;       // sg ping-pong offset

using u64 = unsigned long long;

__device__ __forceinline__ u64 ffma2(u64 a, u64 b, u64 c) {
    u64 d;
    asm("fma.rn.f32x2 %0, %1, %2, %3;" : "=l"(d) : "l"(a), "l"(b), "l"(c));
    return d;
}
__device__ __forceinline__ float hsum2(u64 v) {
    float lo, hi;
    asm("mov.b64 {%0, %1}, %2;" : "=f"(lo), "=f"(hi) : "l"(v));
    return lo + hi;
}
__device__ __forceinline__ float tanh_a(float x) {
    float y;
    asm("tanh.approx.f32 %0, %1;" : "=f"(y) : "f"(x));
    return y;
}
__device__ __forceinline__ float sig_a(float x) {
    return fmaf(tanh_a(0.5f * x), 0.5f, 0.5f);
}
__device__ __forceinline__ void bar_sync(int id, int cnt) {
    asm volatile("bar.sync %0, %1;" :: "r"(id), "r"(cnt) : "memory");
}
__device__ __forceinline__ void bar_arrive(int id, int cnt) {
    asm volatile("bar.arrive %0, %1;" :: "r"(id), "r"(cnt) : "memory");
}

// Per-thread weights: 4 gate rows of unit U, k-quarter q (chunk-rotated).
struct WReg {
    u64  wh[4][8];
    u64  wx[4];
    float bi[4];
};

__device__ __forceinline__ void load_w(
    const float* __restrict__ Whh, const float* __restrict__ Wih,
    const float* __restrict__ bih, const float* __restrict__ bhh,
    int U, int q, WReg& W)
{
#pragma unroll
    for (int g = 0; g < 4; g++) {
        const int row = 64 * g + U;
        const float* base = Whh + row * H + 16 * q;
#pragma unroll
        for (int c = 0; c < 4; c++) {
            const int cc = (c + q) & 3;
            ulonglong2 v = __ldg((const ulonglong2*)(base + 4 * cc));
            W.wh[g][2 * c]     = v.x;
            W.wh[g][2 * c + 1] = v.y;
        }
        W.wx[g] = __ldg((const u64*)(Wih + row * Fd) + q);
        W.bi[g] = bih[row] + bhh[row];
    }
}

// Partials for all NB_ rows; x from registers; writes float4 per (b,U) to sgq.
template<int NB_>
__device__ __forceinline__ void gate_partials(
    const WReg& W, const float (*__restrict__ sh)[HP],
    const u64* __restrict__ xc,
    float* __restrict__ sgq, int U, int q)
{
#pragma unroll
    for (int b = 0; b < NB_; b++) {
        u64 a0 = 0, a1 = 0, a2 = 0, a3 = 0;
        const u64 xv = xc[b];
        a0 = ffma2(W.wx[0], xv, a0);
        a1 = ffma2(W.wx[1], xv, a1);
        a2 = ffma2(W.wx[2], xv, a2);
        a3 = ffma2(W.wx[3], xv, a3);
        const float* hb = &sh[b][16 * q];
#pragma unroll
        for (int c = 0; c < 4; c++) {
            const int cc = (c + q) & 3;
            ulonglong2 hv = *(const ulonglong2*)(hb + 4 * cc);
            a0 = ffma2(W.wh[0][2 * c], hv.x, a0);
            a1 = ffma2(W.wh[1][2 * c], hv.x, a1);
            a2 = ffma2(W.wh[2][2 * c], hv.x, a2);
            a3 = ffma2(W.wh[3][2 * c], hv.x, a3);
            a0 = ffma2(W.wh[0][2 * c + 1], hv.y, a0);
            a1 = ffma2(W.wh[1][2 * c + 1], hv.y, a1);
            a2 = ffma2(W.wh[2][2 * c + 1], hv.y, a2);
            a3 = ffma2(W.wh[3][2 * c + 1], hv.y, a3);
        }
        *(float4*)&sgq[b * SGS + U * 4] =
            make_float4(hsum2(a0), hsum2(a1), hsum2(a2), hsum2(a3));
    }
}

__device__ __forceinline__ void activation(
    const float* __restrict__ sgh, const WReg& W,
    float (*__restrict__ shB)[HP], int U, int r, float& c)
{
    const int base = r * SGS + U * 4;
    float4 s0 = *(const float4*)&sgh[0 * QS + base];
    float4 s1 = *(const float4*)&sgh[1 * QS + base];
    float4 s2 = *(const float4*)&sgh[2 * QS + base];
    float4 s3 = *(const float4*)&sgh[3 * QS + base];
    float gi = s0.x + s1.x + s2.x + s3.x + W.bi[0];
    float gf = s0.y + s1.y + s2.y + s3.y + W.bi[1];
    float gg = s0.z + s1.z + s2.z + s3.z + W.bi[2];
    float go = s0.w + s1.w + s2.w + s3.w + W.bi[3];
    c = sig_a(gf) * c + sig_a(gi) * tanh_a(gg);
    shB[r][U] = sig_a(go) * tanh_a(c);
}

template<int NB_>
__device__ __forceinline__ void run_lstm(
    int b0,
    const float* __restrict__ input,
    const float* __restrict__ eWih, const float* __restrict__ eWhh,
    const float* __restrict__ ebih, const float* __restrict__ ebhh,
    const float* __restrict__ dWih, const float* __restrict__ dWhh,
    const float* __restrict__ dbih, const float* __restrict__ dbhh,
    const float* __restrict__ fcW,  const float* __restrict__ fcb,
    float* __restrict__ out,
    float (*__restrict__ sh0)[HP], float (*__restrict__ sh1)[HP],
    float* __restrict__ sg,
    float (*__restrict__ sx)[Fd],
    float (*__restrict__ sfcW)[H], float* __restrict__ sfcb)
{
    const int tid  = threadIdx.x;
    const int lane = tid & 31;
    const int wrp  = tid >> 5;
    const int q    = wrp & 3;            // k-quarter (warp-uniform) & activation row
    const int hh   = wrp >> 2;           // unit half owned
    const int U    = 32 * hh + lane;     // unit (0..63)
    const int r    = q;                  // activation batch row
    const int BG   = 1 + hh;             // group partials barrier (128)
    const int BHp  = 3 + hh;             // h-half barrier: producer role
    const int BHc  = 3 + (q >> 1);       // h-half barrier: consumer role

    ((float*)sfcW)[tid]      = fcW[tid];
    ((float*)sfcW)[tid + NT] = fcW[tid + NT];
    if (tid < Fd) sfcb[tid] = fcb[tid];

    if (r < NB_) sh0[r][U] = 0.0f;
    float c = 0.0f;

    WReg W;
    load_w(eWhh, eWih, ebih, ebhh, U, q, W);

    // x base pointers: warp-uniform broadcast loads (2 feats [2q,2q+1])
    const u64* xp[NBMAX];
#pragma unroll
    for (int b = 0; b < NB_; b++)
        xp[b] = (const u64*)(input + (size_t)(b0 + b) * Tn * Fd + 2 * q);

    u64 xc[NBMAX], xn[NBMAX];
#pragma unroll
    for (int b = 0; b < NB_; b++) xc[b] = __ldg(xp[b]);   // x(0)

    float (*shA)[HP] = sh0;
    float (*shB)[HP] = sh1;

    __syncthreads();             // h-zero + fcW visible
    bar_arrive(BHp, 256);        // prologue: publish h(-1)=0 for my half

    // ============ encoder: group-decoupled named barriers ============
    for (int t = 0; t < Tn; t++) {
        if (t + 1 < Tn) {
#pragma unroll
            for (int b = 0; b < NB_; b++) xn[b] = __ldg(xp[b] + (size_t)(t + 1) * 4);
        }
        bar_sync(BHc, 256);      // my h-half (prev step) published

        gate_partials<NB_>(W, shA, xc, sg + (t & 1) * SGH + q * QS, U, q);
#pragma unroll
        for (int b = 0; b < NB_; b++) xc[b] = xn[b];

        bar_sync(BG, 128);       // group partials rendezvous
        if (r < NB_) activation(sg + (t & 1) * SGH, W, shB, U, r, c);
        bar_arrive(BHp, 256);    // publish my h-half

        float (*tmp)[HP] = shA; shA = shB; shB = tmp;
    }

    // ============ decoder: simple full barriers (64 steps) ============
    load_w(dWhh, dWih, dbih, dbhh, U, q, W);

    const bool xth = tid < NB_ * Fd;
    const int  xb  = tid >> 3;
    const int  xf  = tid & 7;
    if (xth)   // x_last = input[:, T-1, :]
        sx[xb][xf] = __ldg(input + ((size_t)(b0 + xb) * Tn + (Tn - 1)) * Fd + xf);

    for (int p = 0; p < Pn; p++) {
        __syncthreads();         // h in shA, x in sx
        u64 xv[NBMAX];
#pragma unroll
        for (int b = 0; b < NB_; b++) xv[b] = *(const u64*)&sx[b][2 * q];

        gate_partials<NB_>(W, shA, xv, sg + q * QS, U, q);
        __syncthreads();         // partials ready

        if (r < NB_) activation(sg, W, shB, U, r, c);
        __syncthreads();         // h_new ready

        if (xth) {               // pred = h_new @ fcW^T + fcb
            float a = sfcb[xf];
            const float4* hr = (const float4*)&shB[xb][0];
            const float4* wr = (const float4*)&sfcW[xf][0];
#pragma unroll
            for (int k = 0; k < 16; k++) {
                float4 hv = hr[k], wv = wr[k];
                a = fmaf(hv.x, wv.x, a);
                a = fmaf(hv.y, wv.y, a);
                a = fmaf(hv.z, wv.z, a);
                a = fmaf(hv.w, wv.w, a);
            }
            out[((size_t)(b0 + xb) * Pn + p) * Fd + xf] = a;
            sx[xb][xf] = a;
        }
        float (*tmp)[HP] = shA; shA = shB; shB = tmp;
    }
}

__global__ void __launch_bounds__(NT, 2)
seq2seq_lstm_kernel(
    const float* __restrict__ input,
    const float* __restrict__ eWih, const float* __restrict__ eWhh,
    const float* __restrict__ ebih, const float* __restrict__ ebhh,
    const float* __restrict__ dWih, const float* __restrict__ dWhh,
    const float* __restrict__ dbih, const float* __restrict__ dbhh,
    const float* __restrict__ fcW,  const float* __restrict__ fcb,
    float* __restrict__ out)
{
    __shared__ float sh0[NBMAX][HP];
    __shared__ float sh1[NBMAX][HP];
    __shared__ float sg[2 * SGH];
    __shared__ float sx[NBMAX][Fd];
    __shared__ float sfcW[Fd][H];
    __shared__ float sfcb[Fd];

    const int bid = blockIdx.x;
    if (bid < 136) {
        run_lstm<4>(4 * bid, input, eWih, eWhh, ebih, ebhh,
                    dWih, dWhh, dbih, dbhh, fcW, fcb, out,
                    sh0, sh1, sg, sx, sfcW, sfcb);
    } else {
        int b0 = (bid < 148) ? (544 + 3 * (bid - 136))
                             : (580 + 3 * (bid - 148));
        run_lstm<3>(b0, input, eWih, eWhh, ebih, ebhh,
                    dWih, dWhh, dbih, dbhh, fcW, fcb, out,
                    sh0, sh1, sg, sx, sfcW, sfcb);
    }
}

} // anonymous namespace

extern "C" void kernel_launch(void* const* d_in, const int* in_sizes, int n_in,
                              void* d_out, int out_size)
{
    const float* input = (const float*)d_in[0];
    const float* eWih  = (const float*)d_in[1];
    const float* eWhh  = (const float*)d_in[2];
    const float* ebih  = (const float*)d_in[3];
    const float* ebhh  = (const float*)d_in[4];
    const float* dWih  = (const float*)d_in[5];
    const float* dWhh  = (const float*)d_in[6];
    const float* dbih  = (const float*)d_in[7];
    const float* dbhh  = (const float*)d_in[8];
    const float* fcW   = (const float*)d_in[9];
    const float* fcb   = (const float*)d_in[10];
    float* out = (float*)d_out;

    seq2seq_lstm_kernel<<<296, NT>>>(input, eWih, eWhh, ebih, ebhh,
                                     dWih, dWhh, dbih, dbhh, fcW, fcb, out);
}